// round 13
// baseline (speedup 1.0000x reference)
#include <cuda_runtime.h>
#include <cuda_bf16.h>
#include <cstdint>

#define H 256
#define W 256
#define CIN 256
#define COMP 64
#define BATCH 4
#define HW (H * W)

__device__ __nv_bfloat16 g_compb[(size_t)BATCH * COMP * HW];  // 32 MiB (bf16)
__device__ float g_s[(size_t)BATCH * 9 * HW];                 // 9 MiB
__device__ __nv_bfloat16 g_wtb[COMP * CIN];                   // W bf16 [o][c]

__device__ __forceinline__ float2 ffma2(float2 a, float2 b, float2 c) {
    unsigned long long au = *reinterpret_cast<unsigned long long*>(&a);
    unsigned long long bu = *reinterpret_cast<unsigned long long*>(&b);
    unsigned long long cu = *reinterpret_cast<unsigned long long*>(&c);
    unsigned long long du;
    asm("fma.rn.f32x2 %0, %1, %2, %3;" : "=l"(du) : "l"(au), "l"(bu), "l"(cu));
    return *reinterpret_cast<float2*>(&du);
}

__device__ __forceinline__ void cp_async16(uint32_t dst, const void* src) {
    asm volatile("cp.async.ca.shared.global [%0], [%1], 16;"
                 :: "r"(dst), "l"(src) : "memory");
}
#define CP_COMMIT() asm volatile("cp.async.commit_group;" ::: "memory")
#define CP_WAIT(n)  asm volatile("cp.async.wait_group %0;" :: "n"(n) : "memory")

// ---------------------------------------------------------------------------
// Kernel 0: wc (64x256 fp32, [o][c]) -> g_wtb bf16 same layout
// ---------------------------------------------------------------------------
__global__ void k_wt(const float* __restrict__ wc) {
    int e = blockIdx.x * 256 + threadIdx.x;
    g_wtb[e] = __float2bfloat16(wc[e]);
}

// ---------------------------------------------------------------------------
// Kernel 1: 1x1 compression via mma.sync bf16 m16n8k16.
// Epilogue stores g_comp as bf16 pairs (write traffic halved).
// ---------------------------------------------------------------------------
#define WPITCH 264   // bf16 per W row (256 + 8 pad) -> 528 B

__global__ void __launch_bounds__(256, 2) k_compress(const float* __restrict__ x) {
    const int b  = blockIdx.y;
    const int p0 = blockIdx.x * 128;
    const float* xb = x + (size_t)b * CIN * HW;
    __nv_bfloat16* cbb = g_compb + (size_t)b * COMP * HW;

    __shared__ __align__(16) __nv_bfloat16 xs[2][32][136];     // 17408 B
    __shared__ __align__(16) __nv_bfloat16 wsm[COMP][WPITCH];  // 33792 B

    const int tid  = threadIdx.x;
    const int lane = tid & 31;
    const int warp = tid >> 5;
    const int wo = warp >> 2, wp = warp & 3;
    const int g  = lane >> 2;

    const uint32_t xs_base  = (uint32_t)__cvta_generic_to_shared(&xs[0][0][0]);
    const uint32_t wsm_base = (uint32_t)__cvta_generic_to_shared(&wsm[0][0]);

#pragma unroll
    for (int i = 0; i < 8; i++) {
        int idx = tid + i * 256;
        int o  = idx >> 5;
        int ch = idx & 31;
        cp_async16(wsm_base + (uint32_t)(o * (WPITCH * 2) + ch * 16),
                   g_wtb + o * 256 + ch * 8);
    }
    CP_COMMIT();

    const int sc = tid >> 3;
    const int sj = tid & 7;

    float xr[16];
    auto ldx = [&](int chunk) {
        const float* src = xb + (size_t)(chunk * 32 + sc) * HW + p0 + sj * 16;
#pragma unroll
        for (int q = 0; q < 4; q++)
            *(float4*)&xr[q * 4] = *(const float4*)(src + q * 4);
    };
    auto stx = [&](int buf) {
        uint32_t pk[8];
#pragma unroll
        for (int i = 0; i < 8; i++)
            asm("cvt.rn.bf16x2.f32 %0, %1, %2;"
                : "=r"(pk[i]) : "f"(xr[2 * i + 1]), "f"(xr[2 * i]));
        __nv_bfloat16* dst = &xs[buf][sc][sj * 16];
        *(uint4*)dst       = *(uint4*)&pk[0];
        *(uint4*)(dst + 8) = *(uint4*)&pk[4];
    };

    float dacc[2][4][4];
#pragma unroll
    for (int m = 0; m < 2; m++)
#pragma unroll
        for (int n = 0; n < 4; n++)
#pragma unroll
            for (int d = 0; d < 4; d++) dacc[m][n][d] = 0.f;

    ldx(0); stx(0);
    CP_WAIT(0);
    __syncthreads();

    const int arow = (lane & 7) + ((lane >> 3) & 1) * 8;
    const int acol = (lane >> 4) * 16;

    for (int it = 0; it < 8; it++) {
        const int cur = it & 1;
        if (it < 7) ldx(it + 1);

        uint32_t a[2][2][4];
#pragma unroll
        for (int m = 0; m < 2; m++)
#pragma unroll
            for (int k = 0; k < 2; k++) {
                uint32_t addr = wsm_base
                              + (uint32_t)(wo * 32 + m * 16 + arow) * (WPITCH * 2)
                              + (uint32_t)(it * 32 + k * 16) * 2 + acol;
                asm volatile(
                    "ldmatrix.sync.aligned.m8n8.x4.shared.b16 "
                    "{%0,%1,%2,%3}, [%4];"
                    : "=r"(a[m][k][0]), "=r"(a[m][k][1]),
                      "=r"(a[m][k][2]), "=r"(a[m][k][3])
                    : "r"(addr));
            }
        uint32_t bfr[2][2][4];
#pragma unroll
        for (int k = 0; k < 2; k++)
#pragma unroll
            for (int np = 0; np < 2; np++) {
                uint32_t addr = xs_base + (uint32_t)cur * 8704
                              + (uint32_t)(k * 16 + (lane & 15)) * 272
                              + (uint32_t)(wp * 32 + np * 16 + (lane >> 4) * 8) * 2;
                asm volatile(
                    "ldmatrix.sync.aligned.m8n8.x4.trans.shared.b16 "
                    "{%0,%1,%2,%3}, [%4];"
                    : "=r"(bfr[k][np][0]), "=r"(bfr[k][np][1]),
                      "=r"(bfr[k][np][2]), "=r"(bfr[k][np][3])
                    : "r"(addr));
            }
#pragma unroll
        for (int m = 0; m < 2; m++)
#pragma unroll
            for (int n = 0; n < 4; n++)
#pragma unroll
                for (int k = 0; k < 2; k++) {
                    uint32_t b0 = bfr[k][n >> 1][(n & 1) * 2];
                    uint32_t b1 = bfr[k][n >> 1][(n & 1) * 2 + 1];
                    asm volatile(
                        "mma.sync.aligned.m16n8k16.row.col.f32.bf16.bf16.f32 "
                        "{%0,%1,%2,%3}, {%4,%5,%6,%7}, {%8,%9}, {%0,%1,%2,%3};"
                        : "+f"(dacc[m][n][0]), "+f"(dacc[m][n][1]),
                          "+f"(dacc[m][n][2]), "+f"(dacc[m][n][3])
                        : "r"(a[m][k][0]), "r"(a[m][k][1]),
                          "r"(a[m][k][2]), "r"(a[m][k][3]),
                          "r"(b0), "r"(b1));
                }

        if (it < 7) stx(cur ^ 1);
        __syncthreads();
    }

    // epilogue: round fp32 acc -> bf16 pairs, store
#pragma unroll
    for (int m = 0; m < 2; m++) {
        const int o = wo * 32 + m * 16 + g;
#pragma unroll
        for (int n = 0; n < 4; n++) {
            const int p = p0 + wp * 32 + n * 8 + (lane & 3) * 2;
            uint32_t r0, r1;
            asm("cvt.rn.bf16x2.f32 %0, %1, %2;"
                : "=r"(r0) : "f"(dacc[m][n][1]), "f"(dacc[m][n][0]));
            asm("cvt.rn.bf16x2.f32 %0, %1, %2;"
                : "=r"(r1) : "f"(dacc[m][n][3]), "f"(dacc[m][n][2]));
            *(uint32_t*)(cbb + (size_t)o * HW + p) = r0;
            *(uint32_t*)(cbb + (size_t)(o + 8) * HW + p) = r1;
        }
    }
}

// ---------------------------------------------------------------------------
// Kernel 2: 3x3 conv (64->9) + bias + softmax via mma.sync bf16.
// Reads bf16 g_comp directly: 10 aligned LDG.128 per row-task, no cvt.
// ---------------------------------------------------------------------------
__global__ void __launch_bounds__(256, 2) k_convsoft(const float* __restrict__ wg,
                                                     const float* __restrict__ bg) {
    const int b  = blockIdx.z;
    const int h0 = blockIdx.y * 8;
    const int w0 = blockIdx.x * 64;

    __shared__ __align__(16) __nv_bfloat16 wsA[9][16][72];   // 20736 B
    __shared__ __align__(16) __nv_bfloat16 xsb[16][1928];    // 61696 B

    const int tid  = threadIdx.x;
    const int lane = tid & 31;
    const int lh   = tid >> 5;

    const __nv_bfloat16* compb = g_compb + (size_t)b * COMP * HW;

    {
        uint32_t* wz = (uint32_t*)&wsA[0][0][0];
        for (int i = tid; i < 9 * 16 * 72 / 2; i += 256) wz[i] = 0u;
    }
    __syncthreads();
    for (int i = tid; i < 9 * 9 * 64; i += 256) {
        int tap = i / 576;
        int rem = i - tap * 576;
        int kk = rem >> 6;
        int c  = rem & 63;
        wsA[tap][kk][c] = __float2bfloat16(wg[(kk * COMP + c) * 9 + tap]);
    }

    const uint32_t xsb_base = (uint32_t)__cvta_generic_to_shared(&xsb[0][0]);
    const uint32_t wsA_base = (uint32_t)__cvta_generic_to_shared(&wsA[0][0][0]);

    const int cc = tid / 10;
    const int rr = tid - cc * 10;
    const bool cvt_act = (tid < 160);
    const int gh = h0 + rr - 1;
    const bool rowok = ((unsigned)gh < 256u);

    // Q4[i] covers 8 px starting at w0-8+8i (16B aligned since w0 % 64 == 0)
    uint4 Q4[10];
    auto cvload = [&](int kstep) {
        if (!cvt_act) return;
        const __nv_bfloat16* src = compb + (size_t)(kstep * 16 + cc) * HW
                                 + gh * W + (w0 - 8);
        const uint4 z = make_uint4(0u, 0u, 0u, 0u);
        Q4[0] = (rowok && w0 > 0) ? *(const uint4*)src : z;
#pragma unroll
        for (int q = 1; q < 9; q++)
            Q4[q] = rowok ? *(const uint4*)(src + 8 * q) : z;
        Q4[9] = (rowok && w0 < 192) ? *(const uint4*)(src + 72) : z;
    };
    auto cvstore = [&]() {
        if (!cvt_act) return;
        const uint32_t* Qu = (const uint32_t*)&Q4[0];   // Qu[k] = px pair (w0-8+2k)
        uint32_t O[34];                                  // O[j] = odd pair (w0-3+2j)
#pragma unroll
        for (int j = 1; j < 34; j++)
            asm("prmt.b32 %0, %1, %2, 0x5432;" : "=r"(O[j]) : "r"(Qu[j + 2]), "r"(Qu[j + 3]));
        uint32_t dbase = xsb_base + (uint32_t)(cc * 3856 + rr * 384);
#pragma unroll
        for (int t = 0; t < 8; t++) {
            asm volatile("st.shared.v4.b32 [%0], {%1,%2,%3,%4};" ::
              "r"(dbase + t * 16),
              "r"(O[1+4*t]), "r"(O[2+4*t]), "r"(O[3+4*t]), "r"(O[4+4*t]));
            asm volatile("st.shared.v4.b32 [%0], {%1,%2,%3,%4};" ::
              "r"(dbase + 128 + t * 16),
              "r"(Qu[4+4*t]), "r"(Qu[5+4*t]), "r"(Qu[6+4*t]), "r"(Qu[7+4*t]));
            asm volatile("st.shared.v4.b32 [%0], {%1,%2,%3,%4};" ::
              "r"(dbase + 256 + t * 16),
              "r"(O[2+4*t]), "r"(O[3+4*t]), "r"(O[4+4*t]), "r"(O[5+4*t]));
        }
    };

    float dacc[8][4];
#pragma unroll
    for (int i = 0; i < 8; i++)
#pragma unroll
        for (int d = 0; d < 4; d++) dacc[i][d] = 0.f;

    cvload(0);
    cvstore();
    __syncthreads();

    const int arow = (lane & 7) + ((lane >> 3) & 1) * 8;
    const int acol = (lane >> 4) * 16;
    const uint32_t bcol = (uint32_t)((lane >> 4) * 8) * 2;

    for (int kstep = 0; kstep < 4; kstep++) {
        if (kstep < 3) cvload(kstep + 1);

#pragma unroll
        for (int tap = 0; tap < 9; tap++) {
            const int di = tap / 3;
            const int dj = tap - di * 3;
            uint32_t a0, a1, a2, a3;
            {
                uint32_t aaddr = wsA_base + (uint32_t)(tap * 2304 + arow * 144
                               + kstep * 32) + acol;
                asm volatile(
                    "ldmatrix.sync.aligned.m8n8.x4.shared.b16 "
                    "{%0,%1,%2,%3}, [%4];"
                    : "=r"(a0), "=r"(a1), "=r"(a2), "=r"(a3) : "r"(aaddr));
            }
            const uint32_t brow = xsb_base + (uint32_t)((lane & 15) * 3856
                                + (lh + di) * 384 + dj * 128) + bcol;
#pragma unroll
            for (int np = 0; np < 4; np++) {
                uint32_t b0, b1, b2, b3;
                asm volatile(
                    "ldmatrix.sync.aligned.m8n8.x4.trans.shared.b16 "
                    "{%0,%1,%2,%3}, [%4];"
                    : "=r"(b0), "=r"(b1), "=r"(b2), "=r"(b3)
                    : "r"(brow + (uint32_t)(np * 32)));
                asm volatile(
                    "mma.sync.aligned.m16n8k16.row.col.f32.bf16.bf16.f32 "
                    "{%0,%1,%2,%3}, {%4,%5,%6,%7}, {%8,%9}, {%0,%1,%2,%3};"
                    : "+f"(dacc[2*np][0]), "+f"(dacc[2*np][1]),
                      "+f"(dacc[2*np][2]), "+f"(dacc[2*np][3])
                    : "r"(a0), "r"(a1), "r"(a2), "r"(a3), "r"(b0), "r"(b1));
                asm volatile(
                    "mma.sync.aligned.m16n8k16.row.col.f32.bf16.bf16.f32 "
                    "{%0,%1,%2,%3}, {%4,%5,%6,%7}, {%8,%9}, {%0,%1,%2,%3};"
                    : "+f"(dacc[2*np+1][0]), "+f"(dacc[2*np+1][1]),
                      "+f"(dacc[2*np+1][2]), "+f"(dacc[2*np+1][3])
                    : "r"(a0), "r"(a1), "r"(a2), "r"(a3), "r"(b2), "r"(b3));
            }
        }
        __syncthreads();
        if (kstep < 3) cvstore();
        __syncthreads();
    }

    const int row_lo = lane >> 2;
    const bool hi = (row_lo == 0);
    const float bias_lo = bg[row_lo];
    const float bias8 = bg[8];
    float* sb = g_s + (size_t)b * 9 * HW;
    const int pxbase = (h0 + lh) * W + w0 + 2 * (lane & 3);

#pragma unroll
    for (int i = 0; i < 8; i++) {
        float d0 = dacc[i][0] + bias_lo;
        float d1 = dacc[i][1] + bias_lo;
        float d2 = hi ? dacc[i][2] + bias8 : -1e30f;
        float d3 = hi ? dacc[i][3] + bias8 : -1e30f;

        float m0 = fmaxf(d0, d2);
        float m1 = fmaxf(d1, d3);
#pragma unroll
        for (int mk = 4; mk <= 16; mk <<= 1) {
            m0 = fmaxf(m0, __shfl_xor_sync(0xffffffffu, m0, mk));
            m1 = fmaxf(m1, __shfl_xor_sync(0xffffffffu, m1, mk));
        }
        float e0 = __expf(d0 - m0);
        float e1 = __expf(d1 - m1);
        float e2 = hi ? __expf(d2 - m0) : 0.f;
        float e3 = hi ? __expf(d3 - m1) : 0.f;
        float s0 = e0 + e2, s1 = e1 + e3;
#pragma unroll
        for (int mk = 4; mk <= 16; mk <<= 1) {
            s0 += __shfl_xor_sync(0xffffffffu, s0, mk);
            s1 += __shfl_xor_sync(0xffffffffu, s1, mk);
        }
        float i0 = 1.f / s0, i1 = 1.f / s1;
        const int px = pxbase + i * 8;
        *(float2*)(sb + (size_t)row_lo * HW + px) = make_float2(e0 * i0, e1 * i1);
        if (hi)
            *(float2*)(sb + (size_t)8 * HW + px) = make_float2(e2 * i0, e3 * i1);
    }
}

// ---------------------------------------------------------------------------
// Kernel 3: direct-gmem 3x3 weighted aggregation, 2 px x 2 rows per thread,
// channel loop unrolled 4x for MLP.
// ---------------------------------------------------------------------------
__global__ void __launch_bounds__(256, 2) k_aggregate(const float* __restrict__ x,
                                                      float* __restrict__ out) {
    const int bz = blockIdx.z;
    const int b  = bz >> 2;
    const int cg = bz & 3;
    const int h0 = blockIdx.y * 16;
    const int w0 = blockIdx.x * 64;

    const int tid  = threadIdx.x;
    const int lane = tid & 31;
    const int lh   = tid >> 5;
    const int w    = w0 + lane * 2;
    const int h    = h0 + 2 * lh;

    const float HAM[9] = {0.0064f, 0.08f, 0.0064f,
                          0.08f,   1.0f,  0.08f,
                          0.0064f, 0.08f, 0.0064f};
    float2 wR0[9], wR1[9];
    {
        const float* sp0 = g_s + (size_t)b * 9 * HW + (size_t)(h * W + w) * 9;
        const float* sp1 = sp0 + (size_t)W * 9;
        float a0[9], a1[9], b0[9], b1[9];
        float sa0 = 0.f, sa1 = 0.f, sb0 = 0.f, sb1 = 0.f;
#pragma unroll
        for (int t = 0; t < 9; t++) {
            a0[t] = HAM[t] * sp0[t];      sa0 += a0[t];
            a1[t] = HAM[t] * sp0[9 + t];  sa1 += a1[t];
            b0[t] = HAM[t] * sp1[t];      sb0 += b0[t];
            b1[t] = HAM[t] * sp1[9 + t];  sb1 += b1[t];
        }
        float ia0 = 1.f / (sa0 + 1e-8f), ia1 = 1.f / (sa1 + 1e-8f);
        float ib0 = 1.f / (sb0 + 1e-8f), ib1 = 1.f / (sb1 + 1e-8f);
#pragma unroll
        for (int t = 0; t < 9; t++) {
            wR0[t] = make_float2(a0[t] * ia0, a1[t] * ia1);
            wR1[t] = make_float2(b0[t] * ib0, b1[t] * ib1);
        }
    }

    const int ra = (h == 0) ? 1 : h - 1;
    const int rd = (h + 1 == 255) ? 254 : h + 2;
    const int wl = (w == 0)   ? 1   : w - 1;
    const int wr = (w == 254) ? 254 : w + 2;
    const int oa = ra * W, ob2 = h * W, oc = (h + 1) * W, od = rd * W;

    const float* xb = x  + ((size_t)b * CIN + cg * 64) * HW;
    float*       ob = out + ((size_t)b * CIN + cg * 64) * HW;

#pragma unroll 4
    for (int c = 0; c < 64; c++) {
        const float* pc = xb + (size_t)c * HW;
        float2 A2 = *(const float2*)(pc + oa + w);
        float  Al = pc[oa + wl], Ar = pc[oa + wr];
        float2 B2 = *(const float2*)(pc + ob2 + w);
        float  Bl = pc[ob2 + wl], Br = pc[ob2 + wr];
        float2 C2 = *(const float2*)(pc + oc + w);
        float  Cl = pc[oc + wl], Cr = pc[oc + wr];
        float2 D2 = *(const float2*)(pc + od + w);
        float  Dl = pc[od + wl], Dr = pc[od + wr];

        float2 g0 = make_float2(0.f, 0.f);
        g0 = ffma2(make_float2(Al,  A2.x), wR0[0], g0);
        g0 = ffma2(A2,                     wR0[1], g0);
        g0 = ffma2(make_float2(A2.y, Ar),  wR0[2], g0);
        g0 = ffma2(make_float2(Bl,  B2.x), wR0[3], g0);
        g0 = ffma2(B2,                     wR0[4], g0);
        g0 = ffma2(make_float2(B2.y, Br),  wR0[5], g0);
        g0 = ffma2(make_float2(Cl,  C2.x), wR0[6], g0);
        g0 = ffma2(C2,                     wR0[7], g0);
        g0 = ffma2(make_float2(C2.y, Cr),  wR0[8], g0);

        float2 g1 = make_float2(0.f, 0.f);
        g1 = ffma2(make_float2(Bl,  B2.x), wR1[0], g1);
        g1 = ffma2(B2,                     wR1[1], g1);
        g1 = ffma2(make_float2(B2.y, Br),  wR1[2], g1);
        g1 = ffma2(make_float2(Cl,  C2.x), wR1[3], g1);
        g1 = ffma2(C2,                     wR1[4], g1);
        g1 = ffma2(make_float2(C2.y, Cr),  wR1[5], g1);
        g1 = ffma2(make_float2(Dl,  D2.x), wR1[6], g1);
        g1 = ffma2(D2,                     wR1[7], g1);
        g1 = ffma2(make_float2(D2.y, Dr),  wR1[8], g1);

        float* po = ob + (size_t)c * HW;
        *(float2*)(po + ob2 + w) = make_float2(2.f * B2.x - g0.x,
                                               2.f * B2.y - g0.y);
        *(float2*)(po + oc + w)  = make_float2(2.f * C2.x - g1.x,
                                               2.f * C2.y - g1.y);
    }
}

// ---------------------------------------------------------------------------
extern "C" void kernel_launch(void* const* d_in, const int* in_sizes, int n_in,
                              void* d_out, int out_size) {
    const float* x  = (const float*)d_in[0];
    const float* wc = (const float*)d_in[1];
    const float* wg = (const float*)d_in[2];
    const float* bg = (const float*)d_in[3];
    float* out = (float*)d_out;

    k_wt       <<<64, 256>>>(wc);
    k_compress <<<dim3(HW / 128, BATCH), 256>>>(x);
    k_convsoft <<<dim3(W / 64, H / 8, BATCH), 256>>>(wg, bg);
    k_aggregate<<<dim3(W / 64, H / 16, BATCH * 4), 256>>>(x, out);
}

// round 14
// speedup vs baseline: 1.0455x; 1.0455x over previous
#include <cuda_runtime.h>
#include <cuda_bf16.h>
#include <cstdint>

#define H 256
#define W 256
#define CIN 256
#define COMP 64
#define BATCH 4
#define HW (H * W)

__device__ __nv_bfloat16 g_compb[(size_t)BATCH * COMP * HW];  // 32 MiB (bf16)
__device__ float g_s[(size_t)BATCH * 9 * HW];                 // 9 MiB
__device__ __nv_bfloat16 g_wtb[COMP * CIN];                   // W bf16 [o][c]

__device__ __forceinline__ float2 ffma2(float2 a, float2 b, float2 c) {
    unsigned long long au = *reinterpret_cast<unsigned long long*>(&a);
    unsigned long long bu = *reinterpret_cast<unsigned long long*>(&b);
    unsigned long long cu = *reinterpret_cast<unsigned long long*>(&c);
    unsigned long long du;
    asm("fma.rn.f32x2 %0, %1, %2, %3;" : "=l"(du) : "l"(au), "l"(bu), "l"(cu));
    return *reinterpret_cast<float2*>(&du);
}

__device__ __forceinline__ void cp_async16(uint32_t dst, const void* src) {
    asm volatile("cp.async.ca.shared.global [%0], [%1], 16;"
                 :: "r"(dst), "l"(src) : "memory");
}
#define CP_COMMIT() asm volatile("cp.async.commit_group;" ::: "memory")
#define CP_WAIT(n)  asm volatile("cp.async.wait_group %0;" :: "n"(n) : "memory")

// ---------------------------------------------------------------------------
// Kernel 0: wc (64x256 fp32, [o][c]) -> g_wtb bf16 same layout
// ---------------------------------------------------------------------------
__global__ void k_wt(const float* __restrict__ wc) {
    int e = blockIdx.x * 256 + threadIdx.x;
    g_wtb[e] = __float2bfloat16(wc[e]);
}

// ---------------------------------------------------------------------------
// Kernel 1: 1x1 compression via mma.sync bf16 m16n8k16.
// Epilogue stores g_comp as bf16 pairs (write traffic halved).
// ---------------------------------------------------------------------------
#define WPITCH 264   // bf16 per W row (256 + 8 pad) -> 528 B

__global__ void __launch_bounds__(256, 2) k_compress(const float* __restrict__ x) {
    const int b  = blockIdx.y;
    const int p0 = blockIdx.x * 128;
    const float* xb = x + (size_t)b * CIN * HW;
    __nv_bfloat16* cbb = g_compb + (size_t)b * COMP * HW;

    __shared__ __align__(16) __nv_bfloat16 xs[2][32][136];     // 17408 B
    __shared__ __align__(16) __nv_bfloat16 wsm[COMP][WPITCH];  // 33792 B

    const int tid  = threadIdx.x;
    const int lane = tid & 31;
    const int warp = tid >> 5;
    const int wo = warp >> 2, wp = warp & 3;
    const int g  = lane >> 2;

    const uint32_t xs_base  = (uint32_t)__cvta_generic_to_shared(&xs[0][0][0]);
    const uint32_t wsm_base = (uint32_t)__cvta_generic_to_shared(&wsm[0][0]);

#pragma unroll
    for (int i = 0; i < 8; i++) {
        int idx = tid + i * 256;
        int o  = idx >> 5;
        int ch = idx & 31;
        cp_async16(wsm_base + (uint32_t)(o * (WPITCH * 2) + ch * 16),
                   g_wtb + o * 256 + ch * 8);
    }
    CP_COMMIT();

    const int sc = tid >> 3;
    const int sj = tid & 7;

    float xr[16];
    auto ldx = [&](int chunk) {
        const float* src = xb + (size_t)(chunk * 32 + sc) * HW + p0 + sj * 16;
#pragma unroll
        for (int q = 0; q < 4; q++)
            *(float4*)&xr[q * 4] = *(const float4*)(src + q * 4);
    };
    auto stx = [&](int buf) {
        uint32_t pk[8];
#pragma unroll
        for (int i = 0; i < 8; i++)
            asm("cvt.rn.bf16x2.f32 %0, %1, %2;"
                : "=r"(pk[i]) : "f"(xr[2 * i + 1]), "f"(xr[2 * i]));
        __nv_bfloat16* dst = &xs[buf][sc][sj * 16];
        *(uint4*)dst       = *(uint4*)&pk[0];
        *(uint4*)(dst + 8) = *(uint4*)&pk[4];
    };

    float dacc[2][4][4];
#pragma unroll
    for (int m = 0; m < 2; m++)
#pragma unroll
        for (int n = 0; n < 4; n++)
#pragma unroll
            for (int d = 0; d < 4; d++) dacc[m][n][d] = 0.f;

    ldx(0); stx(0);
    CP_WAIT(0);
    __syncthreads();

    const int arow = (lane & 7) + ((lane >> 3) & 1) * 8;
    const int acol = (lane >> 4) * 16;

    for (int it = 0; it < 8; it++) {
        const int cur = it & 1;
        if (it < 7) ldx(it + 1);

        uint32_t a[2][2][4];
#pragma unroll
        for (int m = 0; m < 2; m++)
#pragma unroll
            for (int k = 0; k < 2; k++) {
                uint32_t addr = wsm_base
                              + (uint32_t)(wo * 32 + m * 16 + arow) * (WPITCH * 2)
                              + (uint32_t)(it * 32 + k * 16) * 2 + acol;
                asm volatile(
                    "ldmatrix.sync.aligned.m8n8.x4.shared.b16 "
                    "{%0,%1,%2,%3}, [%4];"
                    : "=r"(a[m][k][0]), "=r"(a[m][k][1]),
                      "=r"(a[m][k][2]), "=r"(a[m][k][3])
                    : "r"(addr));
            }
        uint32_t bfr[2][2][4];
#pragma unroll
        for (int k = 0; k < 2; k++)
#pragma unroll
            for (int np = 0; np < 2; np++) {
                uint32_t addr = xs_base + (uint32_t)cur * 8704
                              + (uint32_t)(k * 16 + (lane & 15)) * 272
                              + (uint32_t)(wp * 32 + np * 16 + (lane >> 4) * 8) * 2;
                asm volatile(
                    "ldmatrix.sync.aligned.m8n8.x4.trans.shared.b16 "
                    "{%0,%1,%2,%3}, [%4];"
                    : "=r"(bfr[k][np][0]), "=r"(bfr[k][np][1]),
                      "=r"(bfr[k][np][2]), "=r"(bfr[k][np][3])
                    : "r"(addr));
            }
#pragma unroll
        for (int m = 0; m < 2; m++)
#pragma unroll
            for (int n = 0; n < 4; n++)
#pragma unroll
                for (int k = 0; k < 2; k++) {
                    uint32_t b0 = bfr[k][n >> 1][(n & 1) * 2];
                    uint32_t b1 = bfr[k][n >> 1][(n & 1) * 2 + 1];
                    asm volatile(
                        "mma.sync.aligned.m16n8k16.row.col.f32.bf16.bf16.f32 "
                        "{%0,%1,%2,%3}, {%4,%5,%6,%7}, {%8,%9}, {%0,%1,%2,%3};"
                        : "+f"(dacc[m][n][0]), "+f"(dacc[m][n][1]),
                          "+f"(dacc[m][n][2]), "+f"(dacc[m][n][3])
                        : "r"(a[m][k][0]), "r"(a[m][k][1]),
                          "r"(a[m][k][2]), "r"(a[m][k][3]),
                          "r"(b0), "r"(b1));
                }

        if (it < 7) stx(cur ^ 1);
        __syncthreads();
    }

    // epilogue: round fp32 acc -> bf16 pairs, store
#pragma unroll
    for (int m = 0; m < 2; m++) {
        const int o = wo * 32 + m * 16 + g;
#pragma unroll
        for (int n = 0; n < 4; n++) {
            const int p = p0 + wp * 32 + n * 8 + (lane & 3) * 2;
            uint32_t r0, r1;
            asm("cvt.rn.bf16x2.f32 %0, %1, %2;"
                : "=r"(r0) : "f"(dacc[m][n][1]), "f"(dacc[m][n][0]));
            asm("cvt.rn.bf16x2.f32 %0, %1, %2;"
                : "=r"(r1) : "f"(dacc[m][n][3]), "f"(dacc[m][n][2]));
            *(uint32_t*)(cbb + (size_t)o * HW + p) = r0;
            *(uint32_t*)(cbb + (size_t)(o + 8) * HW + p) = r1;
        }
    }
}

// ---------------------------------------------------------------------------
// Kernel 2: 3x3 conv (64->9) + bias + softmax via mma.sync bf16.
// Reads bf16 g_comp directly: 10 aligned LDG.128 per row-task, no cvt.
// ---------------------------------------------------------------------------
__global__ void __launch_bounds__(256, 2) k_convsoft(const float* __restrict__ wg,
                                                     const float* __restrict__ bg) {
    const int b  = blockIdx.z;
    const int h0 = blockIdx.y * 8;
    const int w0 = blockIdx.x * 64;

    __shared__ __align__(16) __nv_bfloat16 wsA[9][16][72];   // 20736 B
    __shared__ __align__(16) __nv_bfloat16 xsb[16][1928];    // 61696 B

    const int tid  = threadIdx.x;
    const int lane = tid & 31;
    const int lh   = tid >> 5;

    const __nv_bfloat16* compb = g_compb + (size_t)b * COMP * HW;

    {
        uint32_t* wz = (uint32_t*)&wsA[0][0][0];
        for (int i = tid; i < 9 * 16 * 72 / 2; i += 256) wz[i] = 0u;
    }
    __syncthreads();
    for (int i = tid; i < 9 * 9 * 64; i += 256) {
        int tap = i / 576;
        int rem = i - tap * 576;
        int kk = rem >> 6;
        int c  = rem & 63;
        wsA[tap][kk][c] = __float2bfloat16(wg[(kk * COMP + c) * 9 + tap]);
    }

    const uint32_t xsb_base = (uint32_t)__cvta_generic_to_shared(&xsb[0][0]);
    const uint32_t wsA_base = (uint32_t)__cvta_generic_to_shared(&wsA[0][0][0]);

    const int cc = tid / 10;
    const int rr = tid - cc * 10;
    const bool cvt_act = (tid < 160);
    const int gh = h0 + rr - 1;
    const bool rowok = ((unsigned)gh < 256u);

    // Q4[i] covers 8 px starting at w0-8+8i (16B aligned since w0 % 64 == 0)
    uint4 Q4[10];
    auto cvload = [&](int kstep) {
        if (!cvt_act) return;
        const __nv_bfloat16* src = compb + (size_t)(kstep * 16 + cc) * HW
                                 + gh * W + (w0 - 8);
        const uint4 z = make_uint4(0u, 0u, 0u, 0u);
        Q4[0] = (rowok && w0 > 0) ? *(const uint4*)src : z;
#pragma unroll
        for (int q = 1; q < 9; q++)
            Q4[q] = rowok ? *(const uint4*)(src + 8 * q) : z;
        Q4[9] = (rowok && w0 < 192) ? *(const uint4*)(src + 72) : z;
    };
    auto cvstore = [&]() {
        if (!cvt_act) return;
        const uint32_t* Qu = (const uint32_t*)&Q4[0];   // Qu[k] = px pair (w0-8+2k)
        uint32_t O[34];                                  // O[j] = odd pair (w0-3+2j)
#pragma unroll
        for (int j = 1; j < 34; j++)
            asm("prmt.b32 %0, %1, %2, 0x5432;" : "=r"(O[j]) : "r"(Qu[j + 2]), "r"(Qu[j + 3]));
        uint32_t dbase = xsb_base + (uint32_t)(cc * 3856 + rr * 384);
#pragma unroll
        for (int t = 0; t < 8; t++) {
            asm volatile("st.shared.v4.b32 [%0], {%1,%2,%3,%4};" ::
              "r"(dbase + t * 16),
              "r"(O[1+4*t]), "r"(O[2+4*t]), "r"(O[3+4*t]), "r"(O[4+4*t]));
            asm volatile("st.shared.v4.b32 [%0], {%1,%2,%3,%4};" ::
              "r"(dbase + 128 + t * 16),
              "r"(Qu[4+4*t]), "r"(Qu[5+4*t]), "r"(Qu[6+4*t]), "r"(Qu[7+4*t]));
            asm volatile("st.shared.v4.b32 [%0], {%1,%2,%3,%4};" ::
              "r"(dbase + 256 + t * 16),
              "r"(O[2+4*t]), "r"(O[3+4*t]), "r"(O[4+4*t]), "r"(O[5+4*t]));
        }
    };

    float dacc[8][4];
#pragma unroll
    for (int i = 0; i < 8; i++)
#pragma unroll
        for (int d = 0; d < 4; d++) dacc[i][d] = 0.f;

    cvload(0);
    cvstore();
    __syncthreads();

    const int arow = (lane & 7) + ((lane >> 3) & 1) * 8;
    const int acol = (lane >> 4) * 16;
    const uint32_t bcol = (uint32_t)((lane >> 4) * 8) * 2;

    for (int kstep = 0; kstep < 4; kstep++) {
        if (kstep < 3) cvload(kstep + 1);

#pragma unroll
        for (int tap = 0; tap < 9; tap++) {
            const int di = tap / 3;
            const int dj = tap - di * 3;
            uint32_t a0, a1, a2, a3;
            {
                uint32_t aaddr = wsA_base + (uint32_t)(tap * 2304 + arow * 144
                               + kstep * 32) + acol;
                asm volatile(
                    "ldmatrix.sync.aligned.m8n8.x4.shared.b16 "
                    "{%0,%1,%2,%3}, [%4];"
                    : "=r"(a0), "=r"(a1), "=r"(a2), "=r"(a3) : "r"(aaddr));
            }
            const uint32_t brow = xsb_base + (uint32_t)((lane & 15) * 3856
                                + (lh + di) * 384 + dj * 128) + bcol;
#pragma unroll
            for (int np = 0; np < 4; np++) {
                uint32_t b0, b1, b2, b3;
                asm volatile(
                    "ldmatrix.sync.aligned.m8n8.x4.trans.shared.b16 "
                    "{%0,%1,%2,%3}, [%4];"
                    : "=r"(b0), "=r"(b1), "=r"(b2), "=r"(b3)
                    : "r"(brow + (uint32_t)(np * 32)));
                asm volatile(
                    "mma.sync.aligned.m16n8k16.row.col.f32.bf16.bf16.f32 "
                    "{%0,%1,%2,%3}, {%4,%5,%6,%7}, {%8,%9}, {%0,%1,%2,%3};"
                    : "+f"(dacc[2*np][0]), "+f"(dacc[2*np][1]),
                      "+f"(dacc[2*np][2]), "+f"(dacc[2*np][3])
                    : "r"(a0), "r"(a1), "r"(a2), "r"(a3), "r"(b0), "r"(b1));
                asm volatile(
                    "mma.sync.aligned.m16n8k16.row.col.f32.bf16.bf16.f32 "
                    "{%0,%1,%2,%3}, {%4,%5,%6,%7}, {%8,%9}, {%0,%1,%2,%3};"
                    : "+f"(dacc[2*np+1][0]), "+f"(dacc[2*np+1][1]),
                      "+f"(dacc[2*np+1][2]), "+f"(dacc[2*np+1][3])
                    : "r"(a0), "r"(a1), "r"(a2), "r"(a3), "r"(b2), "r"(b3));
            }
        }
        __syncthreads();
        if (kstep < 3) cvstore();
        __syncthreads();
    }

    const int row_lo = lane >> 2;
    const bool hi = (row_lo == 0);
    const float bias_lo = bg[row_lo];
    const float bias8 = bg[8];
    float* sb = g_s + (size_t)b * 9 * HW;
    const int pxbase = (h0 + lh) * W + w0 + 2 * (lane & 3);

#pragma unroll
    for (int i = 0; i < 8; i++) {
        float d0 = dacc[i][0] + bias_lo;
        float d1 = dacc[i][1] + bias_lo;
        float d2 = hi ? dacc[i][2] + bias8 : -1e30f;
        float d3 = hi ? dacc[i][3] + bias8 : -1e30f;

        float m0 = fmaxf(d0, d2);
        float m1 = fmaxf(d1, d3);
#pragma unroll
        for (int mk = 4; mk <= 16; mk <<= 1) {
            m0 = fmaxf(m0, __shfl_xor_sync(0xffffffffu, m0, mk));
            m1 = fmaxf(m1, __shfl_xor_sync(0xffffffffu, m1, mk));
        }
        float e0 = __expf(d0 - m0);
        float e1 = __expf(d1 - m1);
        float e2 = hi ? __expf(d2 - m0) : 0.f;
        float e3 = hi ? __expf(d3 - m1) : 0.f;
        float s0 = e0 + e2, s1 = e1 + e3;
#pragma unroll
        for (int mk = 4; mk <= 16; mk <<= 1) {
            s0 += __shfl_xor_sync(0xffffffffu, s0, mk);
            s1 += __shfl_xor_sync(0xffffffffu, s1, mk);
        }
        float i0 = 1.f / s0, i1 = 1.f / s1;
        const int px = pxbase + i * 8;
        *(float2*)(sb + (size_t)row_lo * HW + px) = make_float2(e0 * i0, e1 * i1);
        if (hi)
            *(float2*)(sb + (size_t)8 * HW + px) = make_float2(e2 * i0, e3 * i1);
    }
}

// ---------------------------------------------------------------------------
// Kernel 3: direct-gmem 3x3 weighted aggregation, 2 px x 2 rows per thread
// (R12 version, unroll 2 — 122 regs, no spills).
// ---------------------------------------------------------------------------
__global__ void __launch_bounds__(256, 2) k_aggregate(const float* __restrict__ x,
                                                      float* __restrict__ out) {
    const int bz = blockIdx.z;
    const int b  = bz >> 2;
    const int cg = bz & 3;
    const int h0 = blockIdx.y * 16;
    const int w0 = blockIdx.x * 64;

    const int tid  = threadIdx.x;
    const int lane = tid & 31;
    const int lh   = tid >> 5;
    const int w    = w0 + lane * 2;
    const int h    = h0 + 2 * lh;

    const float HAM[9] = {0.0064f, 0.08f, 0.0064f,
                          0.08f,   1.0f,  0.08f,
                          0.0064f, 0.08f, 0.0064f};
    float2 wR0[9], wR1[9];
    {
        const float* sp0 = g_s + (size_t)b * 9 * HW + (size_t)(h * W + w) * 9;
        const float* sp1 = sp0 + (size_t)W * 9;
        float a0[9], a1[9], b0[9], b1[9];
        float sa0 = 0.f, sa1 = 0.f, sb0 = 0.f, sb1 = 0.f;
#pragma unroll
        for (int t = 0; t < 9; t++) {
            a0[t] = HAM[t] * sp0[t];      sa0 += a0[t];
            a1[t] = HAM[t] * sp0[9 + t];  sa1 += a1[t];
            b0[t] = HAM[t] * sp1[t];      sb0 += b0[t];
            b1[t] = HAM[t] * sp1[9 + t];  sb1 += b1[t];
        }
        float ia0 = 1.f / (sa0 + 1e-8f), ia1 = 1.f / (sa1 + 1e-8f);
        float ib0 = 1.f / (sb0 + 1e-8f), ib1 = 1.f / (sb1 + 1e-8f);
#pragma unroll
        for (int t = 0; t < 9; t++) {
            wR0[t] = make_float2(a0[t] * ia0, a1[t] * ia1);
            wR1[t] = make_float2(b0[t] * ib0, b1[t] * ib1);
        }
    }

    const int ra = (h == 0) ? 1 : h - 1;
    const int rd = (h + 1 == 255) ? 254 : h + 2;
    const int wl = (w == 0)   ? 1   : w - 1;
    const int wr = (w == 254) ? 254 : w + 2;
    const int oa = ra * W, ob2 = h * W, oc = (h + 1) * W, od = rd * W;

    const float* xb = x  + ((size_t)b * CIN + cg * 64) * HW;
    float*       ob = out + ((size_t)b * CIN + cg * 64) * HW;

#pragma unroll 2
    for (int c = 0; c < 64; c++) {
        const float* pc = xb + (size_t)c * HW;
        float2 A2 = *(const float2*)(pc + oa + w);
        float  Al = pc[oa + wl], Ar = pc[oa + wr];
        float2 B2 = *(const float2*)(pc + ob2 + w);
        float  Bl = pc[ob2 + wl], Br = pc[ob2 + wr];
        float2 C2 = *(const float2*)(pc + oc + w);
        float  Cl = pc[oc + wl], Cr = pc[oc + wr];
        float2 D2 = *(const float2*)(pc + od + w);
        float  Dl = pc[od + wl], Dr = pc[od + wr];

        float2 g0 = make_float2(0.f, 0.f);
        g0 = ffma2(make_float2(Al,  A2.x), wR0[0], g0);
        g0 = ffma2(A2,                     wR0[1], g0);
        g0 = ffma2(make_float2(A2.y, Ar),  wR0[2], g0);
        g0 = ffma2(make_float2(Bl,  B2.x), wR0[3], g0);
        g0 = ffma2(B2,                     wR0[4], g0);
        g0 = ffma2(make_float2(B2.y, Br),  wR0[5], g0);
        g0 = ffma2(make_float2(Cl,  C2.x), wR0[6], g0);
        g0 = ffma2(C2,                     wR0[7], g0);
        g0 = ffma2(make_float2(C2.y, Cr),  wR0[8], g0);

        float2 g1 = make_float2(0.f, 0.f);
        g1 = ffma2(make_float2(Bl,  B2.x), wR1[0], g1);
        g1 = ffma2(B2,                     wR1[1], g1);
        g1 = ffma2(make_float2(B2.y, Br),  wR1[2], g1);
        g1 = ffma2(make_float2(Cl,  C2.x), wR1[3], g1);
        g1 = ffma2(C2,                     wR1[4], g1);
        g1 = ffma2(make_float2(C2.y, Cr),  wR1[5], g1);
        g1 = ffma2(make_float2(Dl,  D2.x), wR1[6], g1);
        g1 = ffma2(D2,                     wR1[7], g1);
        g1 = ffma2(make_float2(D2.y, Dr),  wR1[8], g1);

        float* po = ob + (size_t)c * HW;
        *(float2*)(po + ob2 + w) = make_float2(2.f * B2.x - g0.x,
                                               2.f * B2.y - g0.y);
        *(float2*)(po + oc + w)  = make_float2(2.f * C2.x - g1.x,
                                               2.f * C2.y - g1.y);
    }
}

// ---------------------------------------------------------------------------
extern "C" void kernel_launch(void* const* d_in, const int* in_sizes, int n_in,
                              void* d_out, int out_size) {
    const float* x  = (const float*)d_in[0];
    const float* wc = (const float*)d_in[1];
    const float* wg = (const float*)d_in[2];
    const float* bg = (const float*)d_in[3];
    float* out = (float*)d_out;

    k_wt       <<<64, 256>>>(wc);
    k_compress <<<dim3(HW / 128, BATCH), 256>>>(x);
    k_convsoft <<<dim3(W / 64, H / 8, BATCH), 256>>>(wg, bg);
    k_aggregate<<<dim3(W / 64, H / 16, BATCH * 4), 256>>>(x, out);
}